// round 2
// baseline (speedup 1.0000x reference)
#include <cuda_runtime.h>
#include <math.h>

#define BB 512
#define SS 50
#define DD 100
#define NSN 12
#define LASTN 3
#define NADJN 12
#define SCALEF 0.1f

// Scratch (allocation-free: device globals)
__device__ float g_X[BB * SS * 2 * DD];  // [B*S][200]: h | agg
__device__ float g_G[BB * SS * DD];      // s1 * l2norm(relu([h|agg] @ W_g))

// ---------------------------------------------------------------------------
// K1: per (b,s): gather h row, gather 12 neighbor rows, softmax weights, agg
// ---------------------------------------------------------------------------
__global__ void __launch_bounds__(128) k_gather(
    const int* __restrict__ inputs,
    const float* __restrict__ emb,
    const int* __restrict__ adj_all,
    const float* __restrict__ num_w)
{
    int bs  = blockIdx.x;
    int tid = threadIdx.x;
    int node = inputs[bs];
    const float* er = emb + (long long)node * DD;

    __shared__ float alpha[NSN];
    __shared__ int   nid[NSN];
    if (tid < NSN) {
        nid[tid]   = adj_all[(long long)node * NSN + tid];
        alpha[tid] = num_w[(long long)node * NSN + tid];
    }
    __syncthreads();
    if (tid == 0) {
        float m = alpha[0];
        #pragma unroll
        for (int n = 1; n < NSN; n++) m = fmaxf(m, alpha[n]);
        float e[NSN]; float s = 0.f;
        #pragma unroll
        for (int n = 0; n < NSN; n++) { e[n] = expf(alpha[n] - m); s += e[n]; }
        float inv = 1.f / s;
        #pragma unroll
        for (int n = 0; n < NSN; n++) alpha[n] = e[n] * inv;
    }
    __syncthreads();
    if (tid < DD) {
        long long base = (long long)bs * (2 * DD);
        g_X[base + tid] = er[tid];
        float a = 0.f;
        #pragma unroll
        for (int n = 0; n < NSN; n++)
            a = fmaf(alpha[n], emb[(long long)nid[n] * DD + tid], a);
        g_X[base + DD + tid] = a;
    }
}

// ---------------------------------------------------------------------------
// K2: per b: G = s1 * l2norm(relu([h|agg] @ W_g))   ([50,200]@[200,100])
// ---------------------------------------------------------------------------
__global__ void __launch_bounds__(128) k_global(
    const float* __restrict__ Wg,
    const float* __restrict__ sp)
{
    __shared__ __align__(16) float xs[SS * 2 * DD];  // 40KB, reused as out tile
    int b = blockIdx.x, tid = threadIdx.x;

    const float4* src = (const float4*)(g_X + (long long)b * SS * 2 * DD);
    float4* dst = (float4*)xs;
    for (int i = tid; i < SS * 2 * DD / 4; i += blockDim.x) dst[i] = src[i];
    __syncthreads();

    float acc[SS];
    if (tid < DD) {
        #pragma unroll
        for (int r = 0; r < SS; r++) acc[r] = 0.f;
        for (int k4 = 0; k4 < (2 * DD) / 4; k4++) {
            float w0 = Wg[(k4 * 4 + 0) * DD + tid];
            float w1 = Wg[(k4 * 4 + 1) * DD + tid];
            float w2 = Wg[(k4 * 4 + 2) * DD + tid];
            float w3 = Wg[(k4 * 4 + 3) * DD + tid];
            #pragma unroll
            for (int r = 0; r < SS; r++) {
                float4 xv = ((const float4*)(xs + r * 2 * DD))[k4];
                acc[r] = fmaf(xv.x, w0, acc[r]);
                acc[r] = fmaf(xv.y, w1, acc[r]);
                acc[r] = fmaf(xv.z, w2, acc[r]);
                acc[r] = fmaf(xv.w, w3, acc[r]);
            }
        }
        #pragma unroll
        for (int r = 0; r < SS; r++) acc[r] = fmaxf(acc[r], 0.f);
    }
    __syncthreads();     // everyone done reading xs
    if (tid < DD) {
        #pragma unroll
        for (int r = 0; r < SS; r++) xs[r * DD + tid] = acc[r];
    }
    __syncthreads();

    float s1 = sp[1];
    int w = tid >> 5, lane = tid & 31;
    for (int r = w; r < SS; r += 4) {
        float ssq = 0.f;
        for (int d = lane; d < DD; d += 32) { float v = xs[r * DD + d]; ssq += v * v; }
        #pragma unroll
        for (int o = 16; o > 0; o >>= 1) ssq += __shfl_xor_sync(0xffffffffu, ssq, o);
        float inv = s1 / fmaxf(sqrtf(ssq), 1e-12f);
        for (int d = lane; d < DD; d += 32)
            g_G[((long long)b * SS + r) * DD + d] = xs[r * DD + d] * inv;
    }
}

// ---------------------------------------------------------------------------
// K3: per b: star branch (STEP=1) fused with final combine -> output [B,S,D]
// ---------------------------------------------------------------------------
__global__ void __launch_bounds__(128) k_star(
    const int*   __restrict__ inputs,
    const float* __restrict__ adjm,
    const float* __restrict__ Wa,
    const float* __restrict__ Wq,
    const float* __restrict__ Wk,
    const float* __restrict__ sp,
    float* __restrict__ out)
{
    __shared__ __align__(16) float hs[SS * DD];  // 20KB: h, later hl
    __shared__ __align__(16) float hA[SS * DD];  // 20KB: h @ W_star_a
    __shared__ float star[DD], skv[DD], vv[DD], gate[SS], msk[SS];
    __shared__ float denom_sh;

    int b = blockIdx.x, tid = threadIdx.x;

    // load h rows (stride-2D source)
    for (int i = tid; i < SS * DD; i += blockDim.x) {
        int r = i / DD, d = i - r * DD;
        hs[i] = g_X[(long long)(b * SS + r) * (2 * DD) + d];
    }
    if (tid < SS) msk[tid] = (inputs[b * SS + tid] != 0) ? 1.f : 0.f;
    __syncthreads();

    if (tid == 0) {
        float c = 0.f;
        #pragma unroll
        for (int r = 0; r < SS; r++) c += msk[r];
        denom_sh = fmaxf(c, 1.f);
    }
    __syncthreads();

    if (tid < DD) {                           // star = masked mean
        float s = 0.f;
        for (int r = 0; r < SS; r++) s = fmaf(hs[r * DD + tid], msk[r], s);
        star[tid] = s / denom_sh;
    }
    __syncthreads();

    if (tid < DD) {                           // sk = star @ Wk
        float a = 0.f;
        for (int i = 0; i < DD; i++) a = fmaf(star[i], Wk[i * DD + tid], a);
        skv[tid] = a;
    }
    __syncthreads();

    if (tid < DD) {                           // v = Wq @ sk
        float a = 0.f;
        for (int j = 0; j < DD; j++) a = fmaf(Wq[tid * DD + j], skv[j], a);
        vv[tid] = a;
    }
    __syncthreads();

    if (tid < SS) {                           // gate_s = sigmoid(h_s . v * scale)
        float a = 0.f;
        for (int d = 0; d < DD; d++) a = fmaf(hs[tid * DD + d], vv[d], a);
        gate[tid] = 1.f / (1.f + expf(-a * SCALEF));
    }

    float acc[SS];                            // hA = h @ Wa  ([50,100]@[100,100])
    if (tid < DD) {
        #pragma unroll
        for (int r = 0; r < SS; r++) acc[r] = 0.f;
        for (int k4 = 0; k4 < DD / 4; k4++) {
            float w0 = Wa[(k4 * 4 + 0) * DD + tid];
            float w1 = Wa[(k4 * 4 + 1) * DD + tid];
            float w2 = Wa[(k4 * 4 + 2) * DD + tid];
            float w3 = Wa[(k4 * 4 + 3) * DD + tid];
            #pragma unroll
            for (int r = 0; r < SS; r++) {
                float4 xv = ((const float4*)(hs + r * DD))[k4];
                acc[r] = fmaf(xv.x, w0, acc[r]);
                acc[r] = fmaf(xv.y, w1, acc[r]);
                acc[r] = fmaf(xv.z, w2, acc[r]);
                acc[r] = fmaf(xv.w, w3, acc[r]);
            }
        }
        #pragma unroll
        for (int r = 0; r < SS; r++) hA[r * DD + tid] = acc[r];
    }
    __syncthreads();   // hA ready; everyone done reading hs for gate/star

    if (tid < DD) {    // hl = (1-gate) * (adj @ hA) + gate * star   (overwrite hs)
        const float* adjb = adjm + (long long)b * SS * SS;
        float st = star[tid];
        for (int s2 = 0; s2 < SS; s2++) {
            float hn = 0.f;
            for (int t = 0; t < SS; t++)
                hn = fmaf(adjb[s2 * SS + t], hA[t * DD + tid], hn);
            float g = gate[s2];
            hs[s2 * DD + tid] = (1.f - g) * hn + g * st;
        }
    }
    __syncthreads();

    // output = s0 * l2norm(hl) + G
    float s0 = sp[0];
    int w = tid >> 5, lane = tid & 31;
    for (int r = w; r < SS; r += 4) {
        float ssq = 0.f;
        for (int d = lane; d < DD; d += 32) { float v = hs[r * DD + d]; ssq += v * v; }
        #pragma unroll
        for (int o = 16; o > 0; o >>= 1) ssq += __shfl_xor_sync(0xffffffffu, ssq, o);
        float inv = s0 / fmaxf(sqrtf(ssq), 1e-12f);
        long long base = ((long long)b * SS + r) * DD;
        for (int d = lane; d < DD; d += 32)
            out[base + d] = hs[r * DD + d] * inv + g_G[base + d];
    }
}

// ---------------------------------------------------------------------------
// K4: per b: last-items attention -> last_hidden [B,D]
// ---------------------------------------------------------------------------
__global__ void __launch_bounds__(128) k_last(
    const int*   __restrict__ last_items,
    const int*   __restrict__ adj_items,
    const float* __restrict__ emb,
    const float* __restrict__ Wl,
    float* __restrict__ out_last)
{
    __shared__ float ith[LASTN * DD];
    __shared__ float ah[LASTN * NADJN * DD];
    __shared__ float q[LASTN * DD];
    __shared__ float att[LASTN][NADJN];
    int b = blockIdx.x, tid = threadIdx.x;

    for (int i = tid; i < LASTN * DD; i += blockDim.x) {
        int l = i / DD, d = i - l * DD;
        ith[i] = emb[(long long)last_items[b * LASTN + l] * DD + d];
    }
    for (int i = tid; i < LASTN * NADJN * DD; i += blockDim.x) {
        int n = i / DD, d = i - n * DD;
        ah[i] = emb[(long long)adj_items[b * LASTN * NADJN + n] * DD + d];
    }
    __syncthreads();

    if (tid < DD) {                       // q = item_h @ W_l
        #pragma unroll
        for (int l = 0; l < LASTN; l++) {
            float a = 0.f;
            for (int k = 0; k < DD; k++) a = fmaf(ith[l * DD + k], Wl[k * DD + tid], a);
            q[l * DD + tid] = a;
        }
    }
    __syncthreads();

    int w = tid >> 5, lane = tid & 31;
    for (int p = w; p < LASTN * NADJN; p += 4) {
        int l = p / NADJN, n = p - l * NADJN;
        float s = 0.f;
        for (int d = lane; d < DD; d += 32) s = fmaf(q[l * DD + d], ah[p * DD + d], s);
        #pragma unroll
        for (int o = 16; o > 0; o >>= 1) s += __shfl_xor_sync(0xffffffffu, s, o);
        if (lane == 0) att[l][n] = s * SCALEF;
    }
    __syncthreads();

    if (tid < LASTN) {                    // softmax over NADJ
        float m = att[tid][0];
        #pragma unroll
        for (int n = 1; n < NADJN; n++) m = fmaxf(m, att[tid][n]);
        float s = 0.f, e[NADJN];
        #pragma unroll
        for (int n = 0; n < NADJN; n++) { e[n] = expf(att[tid][n] - m); s += e[n]; }
        float inv = 1.f / s;
        #pragma unroll
        for (int n = 0; n < NADJN; n++) att[tid][n] = e[n] * inv;
    }
    __syncthreads();

    if (tid < DD) {
        float acc = 0.f;
        #pragma unroll
        for (int l = 0; l < LASTN; l++) {
            float a = ith[l * DD + tid];
            #pragma unroll
            for (int n = 0; n < NADJN; n++)
                a = fmaf(att[l][n], ah[(l * NADJN + n) * DD + tid], a);
            acc += a;
        }
        out_last[(long long)b * DD + tid] = acc * (1.f / 3.f);
    }
}

// ---------------------------------------------------------------------------
extern "C" void kernel_launch(void* const* d_in, const int* in_sizes, int n_in,
                              void* d_out, int out_size)
{
    const int*   inputs     = (const int*)d_in[0];
    const float* adjm       = (const float*)d_in[1];
    /* d_in[2] = item (unused by the reference) */
    const int*   last_items = (const int*)d_in[3];
    const int*   adj_items  = (const int*)d_in[4];
    const float* emb        = (const float*)d_in[5];
    const float* sp         = (const float*)d_in[6];
    const float* Wa         = (const float*)d_in[7];
    const float* Wq         = (const float*)d_in[8];
    const float* Wk         = (const float*)d_in[9];
    const float* Wg         = (const float*)d_in[10];
    const float* Wl         = (const float*)d_in[11];
    const int*   adj_all    = (const int*)d_in[12];
    const float* num_w      = (const float*)d_in[13];
    float* out = (float*)d_out;

    k_gather<<<BB * SS, 128>>>(inputs, emb, adj_all, num_w);
    k_global<<<BB, 128>>>(Wg, sp);
    k_star<<<BB, 128>>>(inputs, adjm, Wa, Wq, Wk, sp, out);
    k_last<<<BB, 128>>>(last_items, adj_items, emb, Wl,
                        out + (long long)BB * SS * DD);
}

// round 5
// speedup vs baseline: 1.2476x; 1.2476x over previous
#include <cuda_runtime.h>
#include <math.h>

#define BB 512
#define SS 50
#define DD 100
#define NSN 12
#define LASTN 3
#define NADJN 12
#define SCALEF 0.1f

typedef unsigned long long ull;

__device__ __forceinline__ ull pack2(float lo, float hi) {
    ull r; asm("mov.b64 %0, {%1, %2};" : "=l"(r) : "f"(lo), "f"(hi)); return r;
}
__device__ __forceinline__ void unpack2(ull v, float &lo, float &hi) {
    asm("mov.b64 {%0, %1}, %2;" : "=f"(lo), "=f"(hi) : "l"(v));
}
// packed d = a*b + d (2x fp32 per instr, round-to-nearest each lane)
__device__ __forceinline__ void ffma2(ull &d, ull a, ull b) {
    asm("fma.rn.f32x2 %0, %1, %2, %0;" : "+l"(d) : "l"(a), "l"(b));
}

// smem float offsets
#define OFF_A     0          // 5000: h transposed  [d][s]  -> later G row-major [s][d]
#define OFF_B     5000       // 5000: adjP (float2 dup)     -> later agg transposed [d][s]
#define OFF_C     10000      // 5000: hA row-major [t][d]   -> later hl row-major [s][d]
#define OFF_STAR  15000      // 100
#define OFF_SKV   15100      // 100
#define OFF_VV    15200      // 100
#define OFF_GATE  15300      // 64
#define OFF_MSK   15364      // 64
#define OFF_ALPH  15428      // 600
#define OFF_NID   16028      // 600 (int)
#define OFF_SNODE 16628      // 64  (int)
#define OFF_DEN   16692      // 1
#define SMEM_FLOATS 16704
#define SMEM_BYTES  (SMEM_FLOATS * 4)

__global__ void __launch_bounds__(256) k_fused(
    const int*   __restrict__ inputs,
    const float* __restrict__ adjm,
    const int*   __restrict__ last_items,
    const int*   __restrict__ adj_items,
    const float* __restrict__ emb,
    const float* __restrict__ sp,
    const float* __restrict__ Wa,
    const float* __restrict__ Wq,
    const float* __restrict__ Wk,
    const float* __restrict__ Wg,
    const float* __restrict__ Wl,
    const int*   __restrict__ adj_all,
    const float* __restrict__ num_w,
    float* __restrict__ out)
{
    extern __shared__ float sm[];
    int tid = threadIdx.x;
    int bid = blockIdx.x;

    if (bid < BB) {
        // ================= main branch: per-batch fused pipeline =================
        int b = bid;
        float* A    = sm + OFF_A;
        float* Bf   = sm + OFF_B;
        float* C    = sm + OFF_C;
        float* star = sm + OFF_STAR;
        float* skv  = sm + OFF_SKV;
        float* vv   = sm + OFF_VV;
        float* gate = sm + OFF_GATE;
        float* msk  = sm + OFF_MSK;
        float* alph = sm + OFF_ALPH;
        int*   nid  = (int*)(sm + OFF_NID);
        int*   snode= (int*)(sm + OFF_SNODE);
        float* denp = sm + OFF_DEN;

        // ---- P0: nodes + mask ----
        if (tid < SS) {
            int nd = inputs[b * SS + tid];
            snode[tid] = nd;
            msk[tid] = (nd != 0) ? 1.f : 0.f;
        }
        __syncthreads();

        // ---- P1: gather h (transposed), neighbor ids/weights, adjP ----
        if (tid == 0) {
            float c = 0.f;
            #pragma unroll
            for (int s = 0; s < SS; s++) c += msk[s];
            denp[0] = fmaxf(c, 1.f);
        }
        for (int i = tid; i < SS * DD; i += 256) {
            int s = i / DD, d = i - s * DD;
            A[d * SS + s] = emb[(long long)snode[s] * DD + d];
        }
        for (int i = tid; i < SS * NSN; i += 256) {
            int s = i / NSN, n = i - s * NSN;
            long long nd = snode[s];
            nid[i]  = adj_all[nd * NSN + n];
            alph[i] = num_w[nd * NSN + n];
        }
        {
            const float* ab = adjm + (long long)b * SS * SS;
            float2* adjP = (float2*)Bf;
            for (int i = tid; i < SS * SS; i += 256) {
                float a = ab[i];
                adjP[i] = make_float2(a, a);
            }
        }
        __syncthreads();

        // ---- P2: alpha softmax (tid<50) | star vector (tid 128..227) ----
        if (tid < SS) {
            float* ar = alph + tid * NSN;
            float m = ar[0];
            #pragma unroll
            for (int n = 1; n < NSN; n++) m = fmaxf(m, ar[n]);
            float e[NSN], ssum = 0.f;
            #pragma unroll
            for (int n = 0; n < NSN; n++) { e[n] = expf(ar[n] - m); ssum += e[n]; }
            float inv = 1.f / ssum;
            #pragma unroll
            for (int n = 0; n < NSN; n++) ar[n] = e[n] * inv;
        } else if (tid >= 128 && tid < 128 + DD) {
            int d = tid - 128;
            float s = 0.f;
            #pragma unroll 5
            for (int r = 0; r < SS; r++) s = fmaf(A[d * SS + r], msk[r], s);
            star[d] = s / denp[0];
        }
        __syncthreads();

        // ---- skv = star @ Wk ----
        if (tid < DD) {
            float a = 0.f;
            #pragma unroll 4
            for (int i = 0; i < DD; i++) a = fmaf(star[i], Wk[i * DD + tid], a);
            skv[tid] = a;
        }
        __syncthreads();

        // ---- vv = Wq @ skv ----
        if (tid < DD) {
            float a = 0.f;
            #pragma unroll 4
            for (int j = 0; j < DD; j++) a = fmaf(Wq[tid * DD + j], skv[j], a);
            vv[tid] = a;
        }
        __syncthreads();

        // ---- gate (tid<50)  +  GEMM1: hA = h @ Wa (tid<250) ----
        if (tid < SS) {
            float a = 0.f;
            #pragma unroll 4
            for (int d = 0; d < DD; d++) a = fmaf(A[d * SS + tid], vv[d], a);
            gate[tid] = 1.f / (1.f + expf(-a * SCALEF));
        }
        if (tid < 250) {
            int c2 = tid % 50, g = tid / 50, r0 = g * 10;
            ull acc[5][2];
            #pragma unroll
            for (int rp = 0; rp < 5; rp++) { acc[rp][0] = 0ull; acc[rp][1] = 0ull; }
            const ull* Au = (const ull*)A;
            for (int k = 0; k < DD; k++) {
                float2 w = *(const float2*)&Wa[k * DD + 2 * c2];
                ull wlo = pack2(w.x, w.x), whi = pack2(w.y, w.y);
                const ull* xr = Au + k * (SS / 2) + g * 5;
                #pragma unroll
                for (int rp = 0; rp < 5; rp++) {
                    ull xp = xr[rp];
                    ffma2(acc[rp][0], xp, wlo);
                    ffma2(acc[rp][1], xp, whi);
                }
            }
            #pragma unroll
            for (int rp = 0; rp < 5; rp++) {
                float v0, v1, u0, u1;
                unpack2(acc[rp][0], v0, v1);
                unpack2(acc[rp][1], u0, u1);
                int r = r0 + 2 * rp;
                C[r * DD + 2 * c2]           = v0;
                C[(r + 1) * DD + 2 * c2]     = v1;
                C[r * DD + 2 * c2 + 1]       = u0;
                C[(r + 1) * DD + 2 * c2 + 1] = u1;
            }
        }
        __syncthreads();

        // ---- hn = adj @ hA, hl = (1-g)*hn + g*star (into regs) ----
        float hlv[10][2];
        if (tid < 250) {
            int dp = tid % 50, sg = tid / 50, s0r = sg * 10;
            ull hn[10];
            #pragma unroll
            for (int j = 0; j < 10; j++) hn[j] = 0ull;
            const ull* Cu = (const ull*)C;
            const ull* Bu = (const ull*)Bf;   // adjP, duplicated pairs
            for (int t = 0; t < SS; t++) {
                ull xp = Cu[t * (DD / 2) + dp];
                #pragma unroll
                for (int j = 0; j < 10; j++) {
                    ull ap = Bu[(s0r + j) * SS + t];
                    ffma2(hn[j], xp, ap);
                }
            }
            float st0 = star[2 * dp], st1 = star[2 * dp + 1];
            #pragma unroll
            for (int j = 0; j < 10; j++) {
                float h0, h1;
                unpack2(hn[j], h0, h1);
                float gg = gate[s0r + j];
                hlv[j][0] = (1.f - gg) * h0 + gg * st0;
                hlv[j][1] = (1.f - gg) * h1 + gg * st1;
            }
        }
        __syncthreads();  // all reads of C (hA) and Bf (adjP) complete

        // ---- write hl -> C ; gather agg -> Bf (transposed) ----
        if (tid < 250) {
            int dp = tid % 50, sg = tid / 50, s0r = sg * 10;
            #pragma unroll
            for (int j = 0; j < 10; j++) {
                C[(s0r + j) * DD + 2 * dp]     = hlv[j][0];
                C[(s0r + j) * DD + 2 * dp + 1] = hlv[j][1];
            }
        }
        for (int i = tid; i < SS * DD; i += 256) {
            int s = i / DD, d = i - s * DD;
            const float* ar = alph + s * NSN;
            const int*   nr = nid + s * NSN;
            float a = 0.f;
            #pragma unroll
            for (int n = 0; n < NSN; n++)
                a = fmaf(ar[n], emb[(long long)nr[n] * DD + d], a);
            Bf[d * SS + s] = a;
        }
        __syncthreads();

        // ---- GEMM2: G = relu([h|agg] @ Wg)  (K=200: A then Bf) ----
        ull acc[5][2];
        if (tid < 250) {
            int c2 = tid % 50, g = tid / 50;
            #pragma unroll
            for (int rp = 0; rp < 5; rp++) { acc[rp][0] = 0ull; acc[rp][1] = 0ull; }
            const ull* Au = (const ull*)A;
            const ull* Bu = (const ull*)Bf;
            for (int k = 0; k < DD; k++) {
                float2 w = *(const float2*)&Wg[k * DD + 2 * c2];
                ull wlo = pack2(w.x, w.x), whi = pack2(w.y, w.y);
                const ull* xr = Au + k * (SS / 2) + g * 5;
                #pragma unroll
                for (int rp = 0; rp < 5; rp++) {
                    ull xp = xr[rp];
                    ffma2(acc[rp][0], xp, wlo);
                    ffma2(acc[rp][1], xp, whi);
                }
            }
            for (int k = 0; k < DD; k++) {
                float2 w = *(const float2*)&Wg[(DD + k) * DD + 2 * c2];
                ull wlo = pack2(w.x, w.x), whi = pack2(w.y, w.y);
                const ull* xr = Bu + k * (SS / 2) + g * 5;
                #pragma unroll
                for (int rp = 0; rp < 5; rp++) {
                    ull xp = xr[rp];
                    ffma2(acc[rp][0], xp, wlo);
                    ffma2(acc[rp][1], xp, whi);
                }
            }
        }
        __syncthreads();  // all reads of A complete before overwrite

        if (tid < 250) {
            int c2 = tid % 50, g = tid / 50, r0 = g * 10;
            #pragma unroll
            for (int rp = 0; rp < 5; rp++) {
                float v0, v1, u0, u1;
                unpack2(acc[rp][0], v0, v1);
                unpack2(acc[rp][1], u0, u1);
                int r = r0 + 2 * rp;
                A[r * DD + 2 * c2]           = fmaxf(v0, 0.f);
                A[(r + 1) * DD + 2 * c2]     = fmaxf(v1, 0.f);
                A[r * DD + 2 * c2 + 1]       = fmaxf(u0, 0.f);
                A[(r + 1) * DD + 2 * c2 + 1] = fmaxf(u1, 0.f);
            }
        }
        __syncthreads();

        // ---- final: out = s0 * l2n(hl) + s1 * l2n(G) ----
        float s0 = sp[0], s1 = sp[1];
        int w = tid >> 5, lane = tid & 31;
        for (int r = w; r < SS; r += 8) {
            float ql = 0.f, qg = 0.f;
            for (int d = lane; d < DD; d += 32) {
                float x = C[r * DD + d]; ql = fmaf(x, x, ql);
                float y = A[r * DD + d]; qg = fmaf(y, y, qg);
            }
            #pragma unroll
            for (int o = 16; o > 0; o >>= 1) {
                ql += __shfl_xor_sync(0xffffffffu, ql, o);
                qg += __shfl_xor_sync(0xffffffffu, qg, o);
            }
            float il = s0 / fmaxf(sqrtf(ql), 1e-12f);
            float ig = s1 / fmaxf(sqrtf(qg), 1e-12f);
            long long base = ((long long)b * SS + r) * DD;
            for (int d = lane; d < DD; d += 32)
                out[base + d] = C[r * DD + d] * il + A[r * DD + d] * ig;
        }
    } else {
        // ================= last-items attention branch =================
        int b = bid - BB;
        float* ith = sm;            // 300
        float* ah  = sm + 300;      // 3600
        float* q   = sm + 3900;     // 300
        float* att = sm + 4200;     // 36
        float* out_last = out + (long long)BB * SS * DD;

        for (int i = tid; i < LASTN * DD; i += 256) {
            int l = i / DD, d = i - l * DD;
            ith[i] = emb[(long long)last_items[b * LASTN + l] * DD + d];
        }
        for (int i = tid; i < LASTN * NADJN * DD; i += 256) {
            int n = i / DD, d = i - n * DD;
            ah[i] = emb[(long long)adj_items[b * LASTN * NADJN + n] * DD + d];
        }
        __syncthreads();

        if (tid < DD) {
            #pragma unroll
            for (int l = 0; l < LASTN; l++) {
                float a = 0.f;
                #pragma unroll 4
                for (int k = 0; k < DD; k++)
                    a = fmaf(ith[l * DD + k], Wl[k * DD + tid], a);
                q[l * DD + tid] = a;
            }
        }
        __syncthreads();

        int w = tid >> 5, lane = tid & 31;
        for (int p = w; p < LASTN * NADJN; p += 8) {
            int l = p / NADJN;
            float s = 0.f;
            for (int d = lane; d < DD; d += 32)
                s = fmaf(q[l * DD + d], ah[p * DD + d], s);
            #pragma unroll
            for (int o = 16; o > 0; o >>= 1)
                s += __shfl_xor_sync(0xffffffffu, s, o);
            if (lane == 0) att[p] = s * SCALEF;
        }
        __syncthreads();

        if (tid < LASTN) {
            float* ar = att + tid * NADJN;
            float m = ar[0];
            #pragma unroll
            for (int n = 1; n < NADJN; n++) m = fmaxf(m, ar[n]);
            float e[NADJN], s = 0.f;
            #pragma unroll
            for (int n = 0; n < NADJN; n++) { e[n] = expf(ar[n] - m); s += e[n]; }
            float inv = 1.f / s;
            #pragma unroll
            for (int n = 0; n < NADJN; n++) ar[n] = e[n] * inv;
        }
        __syncthreads();

        if (tid < DD) {
            float acc = 0.f;
            #pragma unroll
            for (int l = 0; l < LASTN; l++) {
                float a = ith[l * DD + tid];
                #pragma unroll
                for (int n = 0; n < NADJN; n++)
                    a = fmaf(att[l * NADJN + n], ah[(l * NADJN + n) * DD + tid], a);
                acc += a;
            }
            out_last[(long long)b * DD + tid] = acc * (1.f / 3.f);
        }
    }
}

extern "C" void kernel_launch(void* const* d_in, const int* in_sizes, int n_in,
                              void* d_out, int out_size)
{
    const int*   inputs     = (const int*)d_in[0];
    const float* adjm       = (const float*)d_in[1];
    /* d_in[2] = item (unused by the reference) */
    const int*   last_items = (const int*)d_in[3];
    const int*   adj_items  = (const int*)d_in[4];
    const float* emb        = (const float*)d_in[5];
    const float* sp         = (const float*)d_in[6];
    const float* Wa         = (const float*)d_in[7];
    const float* Wq         = (const float*)d_in[8];
    const float* Wk         = (const float*)d_in[9];
    const float* Wg         = (const float*)d_in[10];
    const float* Wl         = (const float*)d_in[11];
    const int*   adj_all    = (const int*)d_in[12];
    const float* num_w      = (const float*)d_in[13];
    float* out = (float*)d_out;

    cudaFuncSetAttribute(k_fused, cudaFuncAttributeMaxDynamicSharedMemorySize,
                         SMEM_BYTES);
    k_fused<<<2 * BB, 256, SMEM_BYTES>>>(inputs, adjm, last_items, adj_items,
                                         emb, sp, Wa, Wq, Wk, Wg, Wl,
                                         adj_all, num_w, out);
}

// round 6
// speedup vs baseline: 1.3304x; 1.0664x over previous
#include <cuda_runtime.h>
#include <math.h>

#define BB 512
#define SS 50
#define DD 100
#define NSN 12
#define LASTN 3
#define NADJN 12
#define SCALEF 0.1f

typedef unsigned long long ull;

__device__ __forceinline__ ull pack2(float lo, float hi) {
    ull r; asm("mov.b64 %0, {%1, %2};" : "=l"(r) : "f"(lo), "f"(hi)); return r;
}
__device__ __forceinline__ void unpack2(ull v, float &lo, float &hi) {
    asm("mov.b64 {%0, %1}, %2;" : "=f"(lo), "=f"(hi) : "l"(v));
}
__device__ __forceinline__ void ffma2(ull &d, ull a, ull b) {
    asm("fma.rn.f32x2 %0, %1, %2, %0;" : "+l"(d) : "l"(a), "l"(b));
}

// device scratch (no allocs)
__device__ float g_G[BB * SS * DD];   // s1 * l2norm(relu([h|agg]@Wg))
__device__ float g_MT[DD * DD];       // (Wq @ Wk^T)^T, i.e. MT[i][t] = M[t][i]

// ---- star family smem offsets (floats) ----
#define SA     0        // 5000: h^T [d][s] -> later hl row-major [s][d]
#define SADJ   5000     // 2500: adj row-major [s][t]
#define SC     7500     // 5000: hA row-major [t][d]
#define SSTAR  12500    // 100
#define SVV    12600    // 100
#define SGATE  12700    // 64
#define SMSK   12764    // 64
#define SSNODE 12828    // 64 (int)
#define SDEN   12892    // 1
#define SMEM_FLOATS 12896
#define SMEM_BYTES  (SMEM_FLOATS * 4)

// ---- global family smem offsets ----
#define GA     0        // 5000: h^T [d][s] -> later G row-major [s][d]
#define GB     5000     // 5000: agg^T [d][s]
#define GALPH  10000    // 600
#define GNID   10600    // 600 (int)
#define GSNODE 11200    // 64  (int)

// ===========================================================================
// K0: MT = (Wq @ Wk^T)^T, stored transposed for coalesced matvec reads
// ===========================================================================
__global__ void __launch_bounds__(128) k_prep(
    const float* __restrict__ Wq, const float* __restrict__ Wk)
{
    __shared__ float wq[DD];
    __shared__ float wks[DD * DD];
    int t = blockIdx.x, tid = threadIdx.x;
    for (int i = tid; i < DD; i += 128) wq[i] = Wq[t * DD + i];
    for (int i = tid; i < DD * DD; i += 128) wks[i] = Wk[i];
    __syncthreads();
    if (tid < DD) {
        float a = 0.f;
        #pragma unroll 4
        for (int j = 0; j < DD; j++) a = fmaf(wks[tid * DD + j], wq[j], a);
        g_MT[tid * DD + t] = a;   // MT[i][t]
    }
}

// ===========================================================================
// K1: 512 star blocks | 512 global blocks | 512 last blocks
// ===========================================================================
__global__ void __launch_bounds__(256, 4) k_main(
    const int*   __restrict__ inputs,
    const float* __restrict__ adjm,
    const int*   __restrict__ last_items,
    const int*   __restrict__ adj_items,
    const float* __restrict__ emb,
    const float* __restrict__ sp,
    const float* __restrict__ Wa,
    const float* __restrict__ Wg,
    const float* __restrict__ Wl,
    const int*   __restrict__ adj_all,
    const float* __restrict__ num_w,
    float* __restrict__ out)
{
    extern __shared__ float sm[];
    int tid = threadIdx.x;
    int bid = blockIdx.x;

    if (bid < BB) {
        // ===================== STAR family =====================
        int b = bid;
        float* A    = sm + SA;
        float* ADJ  = sm + SADJ;
        float* C    = sm + SC;
        float* star = sm + SSTAR;
        float* vv   = sm + SVV;
        float* gate = sm + SGATE;
        float* msk  = sm + SMSK;
        int*   snode= (int*)(sm + SSNODE);
        float* denp = sm + SDEN;

        if (tid < SS) {
            int nd = inputs[b * SS + tid];
            snode[tid] = nd;
            msk[tid] = (nd != 0) ? 1.f : 0.f;
        }
        __syncthreads();

        // P1: gather h^T, load adj, denom
        if (tid == 0) {
            float c = 0.f;
            #pragma unroll
            for (int s = 0; s < SS; s++) c += msk[s];
            denp[0] = fmaxf(c, 1.f);
        }
        for (int i = tid; i < SS * DD; i += 256) {
            int s = i / DD, d = i - s * DD;
            A[d * SS + s] = emb[(long long)snode[s] * DD + d];
        }
        {
            const float* ab = adjm + (long long)b * SS * SS;
            for (int i = tid; i < SS * SS; i += 256) ADJ[i] = ab[i];
        }
        __syncthreads();

        // P2: star = masked mean
        if (tid < DD) {
            float s = 0.f;
            #pragma unroll 5
            for (int r = 0; r < SS; r++) s = fmaf(A[tid * SS + r], msk[r], s);
            star[tid] = s / denp[0];
        }
        __syncthreads();

        // P3: vv = M @ star  (coalesced via MT)
        if (tid < DD) {
            float a = 0.f;
            #pragma unroll 4
            for (int i = 0; i < DD; i++) a = fmaf(g_MT[i * DD + tid], star[i], a);
            vv[tid] = a;
        }
        __syncthreads();

        // P4: gate (tid<50) + GEMM1 hA = h @ Wa (tid<250) -> C
        if (tid < SS) {
            float a = 0.f;
            #pragma unroll 4
            for (int d = 0; d < DD; d++) a = fmaf(A[d * SS + tid], vv[d], a);
            gate[tid] = 1.f / (1.f + expf(-a * SCALEF));
        }
        if (tid < 250) {
            int c2 = tid % 50, g = tid / 50, r0 = g * 10;
            ull acc[5][2];
            #pragma unroll
            for (int rp = 0; rp < 5; rp++) { acc[rp][0] = 0ull; acc[rp][1] = 0ull; }
            const ull* Au = (const ull*)A;
            #pragma unroll 2
            for (int k = 0; k < DD; k++) {
                float2 w = *(const float2*)&Wa[k * DD + 2 * c2];
                ull wlo = pack2(w.x, w.x), whi = pack2(w.y, w.y);
                const ull* xr = Au + k * (SS / 2) + g * 5;
                #pragma unroll
                for (int rp = 0; rp < 5; rp++) {
                    ull xp = xr[rp];
                    ffma2(acc[rp][0], xp, wlo);
                    ffma2(acc[rp][1], xp, whi);
                }
            }
            #pragma unroll
            for (int rp = 0; rp < 5; rp++) {
                float v0, v1, u0, u1;
                unpack2(acc[rp][0], v0, v1);
                unpack2(acc[rp][1], u0, u1);
                int r = r0 + 2 * rp;
                C[r * DD + 2 * c2]           = v0;
                C[(r + 1) * DD + 2 * c2]     = v1;
                C[r * DD + 2 * c2 + 1]       = u0;
                C[(r + 1) * DD + 2 * c2 + 1] = u1;
            }
        }
        __syncthreads();

        // P5: hn = adj @ hA, hl = (1-g)*hn + g*star -> write A row-major
        if (tid < 250) {
            int dp = tid % 50, sg = tid / 50, s0r = sg * 10;
            ull hn[10];
            #pragma unroll
            for (int j = 0; j < 10; j++) hn[j] = 0ull;
            const ull* Cu = (const ull*)C;
            #pragma unroll 2
            for (int t = 0; t < SS; t++) {
                ull xp = Cu[t * (DD / 2) + dp];
                #pragma unroll
                for (int j = 0; j < 10; j++) {
                    float a = ADJ[(s0r + j) * SS + t];
                    ffma2(hn[j], xp, pack2(a, a));
                }
            }
            float st0 = star[2 * dp], st1 = star[2 * dp + 1];
            #pragma unroll
            for (int j = 0; j < 10; j++) {
                float h0, h1;
                unpack2(hn[j], h0, h1);
                float gg = gate[s0r + j];
                // A free since P4 barrier: write hl row-major
                A[(s0r + j) * DD + 2 * dp]     = (1.f - gg) * h0 + gg * st0;
                A[(s0r + j) * DD + 2 * dp + 1] = (1.f - gg) * h1 + gg * st1;
            }
        }
        __syncthreads();

        // P6: out = s0 * l2norm(hl)
        float s0 = sp[0];
        int w = tid >> 5, lane = tid & 31;
        for (int r = w; r < SS; r += 8) {
            float q = 0.f;
            for (int d = lane; d < DD; d += 32) {
                float x = A[r * DD + d]; q = fmaf(x, x, q);
            }
            #pragma unroll
            for (int o = 16; o > 0; o >>= 1) q += __shfl_xor_sync(0xffffffffu, q, o);
            float il = s0 / fmaxf(sqrtf(q), 1e-12f);
            long long base = ((long long)b * SS + r) * DD;
            for (int d = lane; d < DD; d += 32)
                out[base + d] = A[r * DD + d] * il;
        }
    } else if (bid < 2 * BB) {
        // ===================== GLOBAL family =====================
        int b = bid - BB;
        float* A    = sm + GA;
        float* Bf   = sm + GB;
        float* alph = sm + GALPH;
        int*   nid  = (int*)(sm + GNID);
        int*   snode= (int*)(sm + GSNODE);

        if (tid < SS) snode[tid] = inputs[b * SS + tid];
        __syncthreads();

        // gather h^T + neighbor meta
        for (int i = tid; i < SS * DD; i += 256) {
            int s = i / DD, d = i - s * DD;
            A[d * SS + s] = emb[(long long)snode[s] * DD + d];
        }
        for (int i = tid; i < SS * NSN; i += 256) {
            int s = i / NSN, n = i - s * NSN;
            long long nd = snode[s];
            nid[i]  = adj_all[nd * NSN + n];
            alph[i] = num_w[nd * NSN + n];
        }
        __syncthreads();

        // softmax over neighbor weights
        if (tid < SS) {
            float* ar = alph + tid * NSN;
            float m = ar[0];
            #pragma unroll
            for (int n = 1; n < NSN; n++) m = fmaxf(m, ar[n]);
            float e[NSN], ssum = 0.f;
            #pragma unroll
            for (int n = 0; n < NSN; n++) { e[n] = expf(ar[n] - m); ssum += e[n]; }
            float inv = 1.f / ssum;
            #pragma unroll
            for (int n = 0; n < NSN; n++) ar[n] = e[n] * inv;
        }
        __syncthreads();

        // gather agg^T
        for (int i = tid; i < SS * DD; i += 256) {
            int s = i / DD, d = i - s * DD;
            const float* ar = alph + s * NSN;
            const int*   nr = nid + s * NSN;
            float a = 0.f;
            #pragma unroll
            for (int n = 0; n < NSN; n++)
                a = fmaf(ar[n], emb[(long long)nr[n] * DD + d], a);
            Bf[d * SS + s] = a;
        }
        __syncthreads();

        // GEMM2: G = relu([h|agg] @ Wg)
        ull acc[5][2];
        if (tid < 250) {
            int c2 = tid % 50, g = tid / 50;
            #pragma unroll
            for (int rp = 0; rp < 5; rp++) { acc[rp][0] = 0ull; acc[rp][1] = 0ull; }
            const ull* Au = (const ull*)A;
            const ull* Bu = (const ull*)Bf;
            #pragma unroll 2
            for (int k = 0; k < DD; k++) {
                float2 w = *(const float2*)&Wg[k * DD + 2 * c2];
                ull wlo = pack2(w.x, w.x), whi = pack2(w.y, w.y);
                const ull* xr = Au + k * (SS / 2) + g * 5;
                #pragma unroll
                for (int rp = 0; rp < 5; rp++) {
                    ull xp = xr[rp];
                    ffma2(acc[rp][0], xp, wlo);
                    ffma2(acc[rp][1], xp, whi);
                }
            }
            #pragma unroll 2
            for (int k = 0; k < DD; k++) {
                float2 w = *(const float2*)&Wg[(DD + k) * DD + 2 * c2];
                ull wlo = pack2(w.x, w.x), whi = pack2(w.y, w.y);
                const ull* xr = Bu + k * (SS / 2) + g * 5;
                #pragma unroll
                for (int rp = 0; rp < 5; rp++) {
                    ull xp = xr[rp];
                    ffma2(acc[rp][0], xp, wlo);
                    ffma2(acc[rp][1], xp, whi);
                }
            }
        }
        __syncthreads();   // reads of A done before overwrite

        if (tid < 250) {
            int c2 = tid % 50, g = tid / 50, r0 = g * 10;
            #pragma unroll
            for (int rp = 0; rp < 5; rp++) {
                float v0, v1, u0, u1;
                unpack2(acc[rp][0], v0, v1);
                unpack2(acc[rp][1], u0, u1);
                int r = r0 + 2 * rp;
                A[r * DD + 2 * c2]           = fmaxf(v0, 0.f);
                A[(r + 1) * DD + 2 * c2]     = fmaxf(v1, 0.f);
                A[r * DD + 2 * c2 + 1]       = fmaxf(u0, 0.f);
                A[(r + 1) * DD + 2 * c2 + 1] = fmaxf(u1, 0.f);
            }
        }
        __syncthreads();

        // g_G = s1 * l2norm(G)
        float s1 = sp[1];
        int w = tid >> 5, lane = tid & 31;
        for (int r = w; r < SS; r += 8) {
            float q = 0.f;
            for (int d = lane; d < DD; d += 32) {
                float y = A[r * DD + d]; q = fmaf(y, y, q);
            }
            #pragma unroll
            for (int o = 16; o > 0; o >>= 1) q += __shfl_xor_sync(0xffffffffu, q, o);
            float ig = s1 / fmaxf(sqrtf(q), 1e-12f);
            long long base = ((long long)b * SS + r) * DD;
            for (int d = lane; d < DD; d += 32)
                g_G[base + d] = A[r * DD + d] * ig;
        }
    } else {
        // ===================== LAST family =====================
        int b = bid - 2 * BB;
        float* ith = sm;            // 300
        float* ah  = sm + 300;      // 3600
        float* q   = sm + 3900;     // 300
        float* att = sm + 4200;     // 36
        float* out_last = out + (long long)BB * SS * DD;

        for (int i = tid; i < LASTN * DD; i += 256) {
            int l = i / DD, d = i - l * DD;
            ith[i] = emb[(long long)last_items[b * LASTN + l] * DD + d];
        }
        for (int i = tid; i < LASTN * NADJN * DD; i += 256) {
            int n = i / DD, d = i - n * DD;
            ah[i] = emb[(long long)adj_items[b * LASTN * NADJN + n] * DD + d];
        }
        __syncthreads();

        if (tid < DD) {
            #pragma unroll
            for (int l = 0; l < LASTN; l++) {
                float a = 0.f;
                #pragma unroll 4
                for (int k = 0; k < DD; k++)
                    a = fmaf(ith[l * DD + k], Wl[k * DD + tid], a);
                q[l * DD + tid] = a;
            }
        }
        __syncthreads();

        int w = tid >> 5, lane = tid & 31;
        for (int p = w; p < LASTN * NADJN; p += 8) {
            int l = p / NADJN;
            float s = 0.f;
            for (int d = lane; d < DD; d += 32)
                s = fmaf(q[l * DD + d], ah[p * DD + d], s);
            #pragma unroll
            for (int o = 16; o > 0; o >>= 1)
                s += __shfl_xor_sync(0xffffffffu, s, o);
            if (lane == 0) att[p] = s * SCALEF;
        }
        __syncthreads();

        if (tid < LASTN) {
            float* ar = att + tid * NADJN;
            float m = ar[0];
            #pragma unroll
            for (int n = 1; n < NADJN; n++) m = fmaxf(m, ar[n]);
            float e[NADJN], s = 0.f;
            #pragma unroll
            for (int n = 0; n < NADJN; n++) { e[n] = expf(ar[n] - m); s += e[n]; }
            float inv = 1.f / s;
            #pragma unroll
            for (int n = 0; n < NADJN; n++) ar[n] = e[n] * inv;
        }
        __syncthreads();

        if (tid < DD) {
            float acc = 0.f;
            #pragma unroll
            for (int l = 0; l < LASTN; l++) {
                float a = ith[l * DD + tid];
                #pragma unroll
                for (int n = 0; n < NADJN; n++)
                    a = fmaf(att[l * NADJN + n], ah[(l * NADJN + n) * DD + tid], a);
                acc += a;
            }
            out_last[(long long)b * DD + tid] = acc * (1.f / 3.f);
        }
    }
}

// ===========================================================================
// K2: out += g_G  (main output region only)
// ===========================================================================
__global__ void __launch_bounds__(256) k_combine(float* __restrict__ out)
{
    int i = blockIdx.x * 256 + threadIdx.x;
    const int n4 = BB * SS * DD / 4;
    if (i < n4) {
        const float4* g4 = (const float4*)g_G;
        float4* o4 = (float4*)out;
        float4 a = o4[i], g = g4[i];
        a.x += g.x; a.y += g.y; a.z += g.z; a.w += g.w;
        o4[i] = a;
    }
}

extern "C" void kernel_launch(void* const* d_in, const int* in_sizes, int n_in,
                              void* d_out, int out_size)
{
    const int*   inputs     = (const int*)d_in[0];
    const float* adjm       = (const float*)d_in[1];
    /* d_in[2] = item (unused by the reference) */
    const int*   last_items = (const int*)d_in[3];
    const int*   adj_items  = (const int*)d_in[4];
    const float* emb        = (const float*)d_in[5];
    const float* sp         = (const float*)d_in[6];
    const float* Wa         = (const float*)d_in[7];
    const float* Wq         = (const float*)d_in[8];
    const float* Wk         = (const float*)d_in[9];
    const float* Wg         = (const float*)d_in[10];
    const float* Wl         = (const float*)d_in[11];
    const int*   adj_all    = (const int*)d_in[12];
    const float* num_w      = (const float*)d_in[13];
    float* out = (float*)d_out;

    cudaFuncSetAttribute(k_main, cudaFuncAttributeMaxDynamicSharedMemorySize,
                         SMEM_BYTES);

    k_prep<<<DD, 128>>>(Wq, Wk);
    k_main<<<3 * BB, 256, SMEM_BYTES>>>(inputs, adjm, last_items, adj_items,
                                        emb, sp, Wa, Wg, Wl,
                                        adj_all, num_w, out);
    int n4 = BB * SS * DD / 4;
    k_combine<<<(n4 + 255) / 256, 256>>>(out);
}

// round 8
// speedup vs baseline: 1.4606x; 1.0979x over previous
#include <cuda_runtime.h>
#include <math.h>

#define BB 512
#define SS 50
#define DD 100
#define NSN 12
#define LASTN 3
#define NADJN 12
#define SCALEF 0.1f

typedef unsigned long long ull;

__device__ __forceinline__ ull pack2(float lo, float hi) {
    ull r; asm("mov.b64 %0, {%1, %2};" : "=l"(r) : "f"(lo), "f"(hi)); return r;
}
__device__ __forceinline__ void unpack2(ull v, float &lo, float &hi) {
    asm("mov.b64 {%0, %1}, %2;" : "=f"(lo), "=f"(hi) : "l"(v));
}
__device__ __forceinline__ void ffma2(ull &d, ull a, ull b) {
    asm("fma.rn.f32x2 %0, %1, %2, %0;" : "+l"(d) : "l"(a), "l"(b));
}
__device__ __forceinline__ void barn(int id) {   // named barrier, 256 threads
    asm volatile("bar.sync %0, 256;" :: "r"(id) : "memory");
}

// smem float offsets (combined block)
#define OA    0        // 5000: h^T [d][s] (read-only after load)
#define OADJ  5000     // 2500: adj row-major
#define OC    7500     // 5000: hA row-major -> hl row-major
#define OAGG  12500    // 5000: agg^T [d][s]
#define OG    17500    // 5000: G row-major [s][d]
#define OSTAR 22500    // 100
#define OSKV  22600    // 100
#define OVV   22700    // 100
#define OGATE 22800    // 64
#define OMSK  22864    // 64
#define OALPH 22928    // 600
#define ONID  23528    // 600 (int)
#define OSNOD 24128    // 64 (int)
#define ODEN  24192    // 1
#define SMEM_FLOATS 24200
#define SMEM_BYTES  (SMEM_FLOATS * 4)

__global__ void __launch_bounds__(512, 2) k_main(
    const int*   __restrict__ inputs,
    const float* __restrict__ adjm,
    const int*   __restrict__ last_items,
    const int*   __restrict__ adj_items,
    const float* __restrict__ emb,
    const float* __restrict__ sp,
    const float* __restrict__ Wa,
    const float* __restrict__ Wq,
    const float* __restrict__ Wk,
    const float* __restrict__ Wg,
    const float* __restrict__ Wl,
    const int*   __restrict__ adj_all,
    const float* __restrict__ num_w,
    float* __restrict__ out)
{
    extern __shared__ float sm[];
    int tid = threadIdx.x;
    int bid = blockIdx.x;

    if (bid < BB) {
        // ============ combined star+global block, 2 concurrent halves ============
        int b = bid;
        float* A    = sm + OA;
        float* ADJ  = sm + OADJ;
        float* C    = sm + OC;
        float* AGG  = sm + OAGG;
        float* G    = sm + OG;
        float* star = sm + OSTAR;
        float* skv  = sm + OSKV;
        float* vv   = sm + OVV;
        float* gate = sm + OGATE;
        float* msk  = sm + OMSK;
        float* alph = sm + OALPH;
        int*   nid  = (int*)(sm + ONID);
        int*   snode= (int*)(sm + OSNOD);
        float* denp = sm + ODEN;

        if (tid < SS) {
            int nd = inputs[b * SS + tid];
            snode[tid] = nd;
            msk[tid] = (nd != 0) ? 1.f : 0.f;
        }
        __syncthreads();

        // ---- shared load phase (all 512 threads) ----
        if (tid == 0) {
            float c = 0.f;
            #pragma unroll
            for (int s = 0; s < SS; s++) c += msk[s];
            denp[0] = fmaxf(c, 1.f);
        }
        for (int i = tid; i < SS * DD; i += 512) {
            int s = i / DD, d = i - s * DD;
            A[d * SS + s] = emb[(long long)snode[s] * DD + d];
        }
        {
            const float* ab = adjm + (long long)b * SS * SS;
            for (int i = tid; i < SS * SS; i += 512) ADJ[i] = ab[i];
        }
        for (int i = tid; i < SS * NSN; i += 512) {
            int s = i / NSN, n = i - s * NSN;
            long long nd = snode[s];
            nid[i]  = adj_all[nd * NSN + n];
            alph[i] = num_w[nd * NSN + n];
        }
        __syncthreads();

        if (tid < 256) {
            // ======================= STAR half (barrier 1) =======================
            int st = tid;
            // P2: star = masked mean
            if (st < DD) {
                float s = 0.f;
                #pragma unroll 5
                for (int r = 0; r < SS; r++) s = fmaf(A[st * SS + r], msk[r], s);
                star[st] = s / denp[0];
            }
            barn(1);
            // P3: skv = star @ Wk (coalesced over t)
            if (st < DD) {
                float a0 = 0.f, a1 = 0.f, a2 = 0.f, a3 = 0.f;
                #pragma unroll 1
                for (int i = 0; i < DD; i += 4) {
                    a0 = fmaf(star[i],     Wk[i * DD + st],       a0);
                    a1 = fmaf(star[i + 1], Wk[(i + 1) * DD + st], a1);
                    a2 = fmaf(star[i + 2], Wk[(i + 2) * DD + st], a2);
                    a3 = fmaf(star[i + 3], Wk[(i + 3) * DD + st], a3);
                }
                skv[st] = (a0 + a1) + (a2 + a3);
            }
            barn(1);
            // P4: vv = Wq @ skv
            if (st < DD) {
                float a0 = 0.f, a1 = 0.f, a2 = 0.f, a3 = 0.f;
                const float* wr = Wq + st * DD;
                #pragma unroll 1
                for (int j = 0; j < DD; j += 4) {
                    a0 = fmaf(wr[j],     skv[j],     a0);
                    a1 = fmaf(wr[j + 1], skv[j + 1], a1);
                    a2 = fmaf(wr[j + 2], skv[j + 2], a2);
                    a3 = fmaf(wr[j + 3], skv[j + 3], a3);
                }
                vv[st] = (a0 + a1) + (a2 + a3);
            }
            barn(1);
            // P5: gate (st<50) + GEMM1 hA = h @ Wa (st<250) -> C
            if (st < SS) {
                float a = 0.f;
                #pragma unroll 4
                for (int d = 0; d < DD; d++) a = fmaf(A[d * SS + st], vv[d], a);
                gate[st] = 1.f / (1.f + expf(-a * SCALEF));
            }
            if (st < 250) {
                int c2 = st % 50, g = st / 50, r0 = g * 10;
                ull acc[5][2];
                #pragma unroll
                for (int rp = 0; rp < 5; rp++) { acc[rp][0] = 0ull; acc[rp][1] = 0ull; }
                const ull* Au = (const ull*)A;
                #pragma unroll 2
                for (int k = 0; k < DD; k++) {
                    float2 w = *(const float2*)&Wa[k * DD + 2 * c2];
                    ull wlo = pack2(w.x, w.x), whi = pack2(w.y, w.y);
                    const ull* xr = Au + k * (SS / 2) + g * 5;
                    #pragma unroll
                    for (int rp = 0; rp < 5; rp++) {
                        ull xp = xr[rp];
                        ffma2(acc[rp][0], xp, wlo);
                        ffma2(acc[rp][1], xp, whi);
                    }
                }
                #pragma unroll
                for (int rp = 0; rp < 5; rp++) {
                    float v0, v1, u0, u1;
                    unpack2(acc[rp][0], v0, v1);
                    unpack2(acc[rp][1], u0, u1);
                    int r = r0 + 2 * rp;
                    C[r * DD + 2 * c2]           = v0;
                    C[(r + 1) * DD + 2 * c2]     = v1;
                    C[r * DD + 2 * c2 + 1]       = u0;
                    C[(r + 1) * DD + 2 * c2 + 1] = u1;
                }
            }
            barn(1);
            // P6: hn = adj @ hA, hl = (1-g)*hn + g*star
            float hlv[10][2];
            int dp = st % 50, sg = st / 50, s0r = sg * 10;
            if (st < 250) {
                ull hn[10];
                #pragma unroll
                for (int j = 0; j < 10; j++) hn[j] = 0ull;
                const ull* Cu = (const ull*)C;
                #pragma unroll 2
                for (int t = 0; t < SS; t++) {
                    ull xp = Cu[t * (DD / 2) + dp];
                    #pragma unroll
                    for (int j = 0; j < 10; j++) {
                        float a = ADJ[(s0r + j) * SS + t];
                        ffma2(hn[j], xp, pack2(a, a));
                    }
                }
                float st0 = star[2 * dp], st1 = star[2 * dp + 1];
                #pragma unroll
                for (int j = 0; j < 10; j++) {
                    float h0, h1;
                    unpack2(hn[j], h0, h1);
                    float gg = gate[s0r + j];
                    hlv[j][0] = (1.f - gg) * h0 + gg * st0;
                    hlv[j][1] = (1.f - gg) * h1 + gg * st1;
                }
            }
            barn(1);   // all reads of C done
            if (st < 250) {
                #pragma unroll
                for (int j = 0; j < 10; j++) {
                    C[(s0r + j) * DD + 2 * dp]     = hlv[j][0];
                    C[(s0r + j) * DD + 2 * dp + 1] = hlv[j][1];
                }
            }
        } else {
            // ====================== GLOBAL half (barrier 2) ======================
            int gt = tid - 256;
            // softmax over neighbor weights
            if (gt < SS) {
                float* ar = alph + gt * NSN;
                float m = ar[0];
                #pragma unroll
                for (int n = 1; n < NSN; n++) m = fmaxf(m, ar[n]);
                float e[NSN], ssum = 0.f;
                #pragma unroll
                for (int n = 0; n < NSN; n++) { e[n] = expf(ar[n] - m); ssum += e[n]; }
                float inv = 1.f / ssum;
                #pragma unroll
                for (int n = 0; n < NSN; n++) ar[n] = e[n] * inv;
            }
            barn(2);
            // gather agg^T (the big 123MB gather)
            for (int i = gt; i < SS * DD; i += 256) {
                int s = i / DD, d = i - s * DD;
                const float* ar = alph + s * NSN;
                const int*   nr = nid + s * NSN;
                float a = 0.f;
                #pragma unroll
                for (int n = 0; n < NSN; n++)
                    a = fmaf(ar[n], emb[(long long)nr[n] * DD + d], a);
                AGG[d * SS + s] = a;
            }
            barn(2);
            // GEMM2: G = relu([h|agg] @ Wg) -> G buffer (distinct, no barrier)
            if (gt < 250) {
                int c2 = gt % 50, g = gt / 50, r0 = g * 10;
                ull acc[5][2];
                #pragma unroll
                for (int rp = 0; rp < 5; rp++) { acc[rp][0] = 0ull; acc[rp][1] = 0ull; }
                const ull* Au = (const ull*)A;
                const ull* Bu = (const ull*)AGG;
                #pragma unroll 2
                for (int k = 0; k < DD; k++) {
                    float2 w = *(const float2*)&Wg[k * DD + 2 * c2];
                    ull wlo = pack2(w.x, w.x), whi = pack2(w.y, w.y);
                    const ull* xr = Au + k * (SS / 2) + g * 5;
                    #pragma unroll
                    for (int rp = 0; rp < 5; rp++) {
                        ull xp = xr[rp];
                        ffma2(acc[rp][0], xp, wlo);
                        ffma2(acc[rp][1], xp, whi);
                    }
                }
                #pragma unroll 2
                for (int k = 0; k < DD; k++) {
                    float2 w = *(const float2*)&Wg[(DD + k) * DD + 2 * c2];
                    ull wlo = pack2(w.x, w.x), whi = pack2(w.y, w.y);
                    const ull* xr = Bu + k * (SS / 2) + g * 5;
                    #pragma unroll
                    for (int rp = 0; rp < 5; rp++) {
                        ull xp = xr[rp];
                        ffma2(acc[rp][0], xp, wlo);
                        ffma2(acc[rp][1], xp, whi);
                    }
                }
                #pragma unroll
                for (int rp = 0; rp < 5; rp++) {
                    float v0, v1, u0, u1;
                    unpack2(acc[rp][0], v0, v1);
                    unpack2(acc[rp][1], u0, u1);
                    int r = r0 + 2 * rp;
                    G[r * DD + 2 * c2]           = fmaxf(v0, 0.f);
                    G[(r + 1) * DD + 2 * c2]     = fmaxf(v1, 0.f);
                    G[r * DD + 2 * c2 + 1]       = fmaxf(u0, 0.f);
                    G[(r + 1) * DD + 2 * c2 + 1] = fmaxf(u1, 0.f);
                }
            }
        }
        __syncthreads();   // halves rendezvous: C = hl, G ready

        // ---- final combine: out = s0*l2n(hl) + s1*l2n(G) (all 16 warps) ----
        float s0 = sp[0], s1 = sp[1];
        int w = tid >> 5, lane = tid & 31;
        for (int r = w; r < SS; r += 16) {
            float ql = 0.f, qg = 0.f;
            for (int d = lane; d < DD; d += 32) {
                float x = C[r * DD + d]; ql = fmaf(x, x, ql);
                float y = G[r * DD + d]; qg = fmaf(y, y, qg);
            }
            #pragma unroll
            for (int o = 16; o > 0; o >>= 1) {
                ql += __shfl_xor_sync(0xffffffffu, ql, o);
                qg += __shfl_xor_sync(0xffffffffu, qg, o);
            }
            float il = s0 / fmaxf(sqrtf(ql), 1e-12f);
            float ig = s1 / fmaxf(sqrtf(qg), 1e-12f);
            long long base = ((long long)b * SS + r) * DD;
            for (int d = lane; d < DD; d += 32)
                out[base + d] = C[r * DD + d] * il + G[r * DD + d] * ig;
        }
    } else {
        // ========================== LAST family ==========================
        int b = bid - BB;
        float* ith = sm;            // 300
        float* ah  = sm + 300;      // 3600
        float* q   = sm + 3900;     // 300
        float* att = sm + 4200;     // 36
        float* out_last = out + (long long)BB * SS * DD;

        for (int i = tid; i < LASTN * DD; i += 512) {
            int l = i / DD, d = i - l * DD;
            ith[i] = emb[(long long)last_items[b * LASTN + l] * DD + d];
        }
        for (int i = tid; i < LASTN * NADJN * DD; i += 512) {
            int n = i / DD, d = i - n * DD;
            ah[i] = emb[(long long)adj_items[b * LASTN * NADJN + n] * DD + d];
        }
        __syncthreads();

        if (tid < DD) {
            #pragma unroll
            for (int l = 0; l < LASTN; l++) {
                float a = 0.f;
                #pragma unroll 4
                for (int k = 0; k < DD; k++)
                    a = fmaf(ith[l * DD + k], Wl[k * DD + tid], a);
                q[l * DD + tid] = a;
            }
        }
        __syncthreads();

        int w = tid >> 5, lane = tid & 31;
        for (int p = w; p < LASTN * NADJN; p += 16) {
            int l = p / NADJN;
            float s = 0.f;
            for (int d = lane; d < DD; d += 32)
                s = fmaf(q[l * DD + d], ah[p * DD + d], s);
            #pragma unroll
            for (int o = 16; o > 0; o >>= 1)
                s += __shfl_xor_sync(0xffffffffu, s, o);
            if (lane == 0) att[p] = s * SCALEF;
        }
        __syncthreads();

        if (tid < LASTN) {
            float* ar = att + tid * NADJN;
            float m = ar[0];
            #pragma unroll
            for (int n = 1; n < NADJN; n++) m = fmaxf(m, ar[n]);
            float e[NADJN], s = 0.f;
            #pragma unroll
            for (int n = 0; n < NADJN; n++) { e[n] = expf(ar[n] - m); s += e[n]; }
            float inv = 1.f / s;
            #pragma unroll
            for (int n = 0; n < NADJN; n++) ar[n] = e[n] * inv;
        }
        __syncthreads();

        if (tid < DD) {
            float acc = 0.f;
            #pragma unroll
            for (int l = 0; l < LASTN; l++) {
                float a = ith[l * DD + tid];
                #pragma unroll
                for (int n = 0; n < NADJN; n++)
                    a = fmaf(att[l * NADJN + n], ah[(l * NADJN + n) * DD + tid], a);
                acc += a;
            }
            out_last[(long long)b * DD + tid] = acc * (1.f / 3.f);
        }
    }
}

extern "C" void kernel_launch(void* const* d_in, const int* in_sizes, int n_in,
                              void* d_out, int out_size)
{
    const int*   inputs     = (const int*)d_in[0];
    const float* adjm       = (const float*)d_in[1];
    /* d_in[2] = item (unused by the reference) */
    const int*   last_items = (const int*)d_in[3];
    const int*   adj_items  = (const int*)d_in[4];
    const float* emb        = (const float*)d_in[5];
    const float* sp         = (const float*)d_in[6];
    const float* Wa         = (const float*)d_in[7];
    const float* Wq         = (const float*)d_in[8];
    const float* Wk         = (const float*)d_in[9];
    const float* Wg         = (const float*)d_in[10];
    const float* Wl         = (const float*)d_in[11];
    const int*   adj_all    = (const int*)d_in[12];
    const float* num_w      = (const float*)d_in[13];
    float* out = (float*)d_out;

    cudaFuncSetAttribute(k_main, cudaFuncAttributeMaxDynamicSharedMemorySize,
                         SMEM_BYTES);
    k_main<<<2 * BB, 512, SMEM_BYTES>>>(inputs, adjm, last_items, adj_items,
                                        emb, sp, Wa, Wq, Wk, Wg, Wl,
                                        adj_all, num_w, out);
}

// round 10
// speedup vs baseline: 1.6325x; 1.1177x over previous
#include <cuda_runtime.h>
#include <math.h>

#define BB 512
#define SS 50
#define DD 100
#define NSN 12
#define LASTN 3
#define NADJN 12
#define SCALEF 0.1f

typedef unsigned long long ull;
typedef long long ll;

__device__ __forceinline__ ull pack2(float lo, float hi) {
    ull r; asm("mov.b64 %0, {%1, %2};" : "=l"(r) : "f"(lo), "f"(hi)); return r;
}
__device__ __forceinline__ void unpack2(ull v, float &lo, float &hi) {
    asm("mov.b64 {%0, %1}, %2;" : "=f"(lo), "=f"(hi) : "l"(v));
}
__device__ __forceinline__ void ffma2(ull &d, ull a, ull b) {
    asm("fma.rn.f32x2 %0, %1, %2, %0;" : "+l"(d) : "l"(a), "l"(b));
}
__device__ __forceinline__ void barn(int id) {   // named barrier, 256 threads
    asm volatile("bar.sync %0, 256;" :: "r"(id) : "memory");
}

// smem float offsets (combined block)
#define OA    0        // 5000: h^T [d][s]
#define OADJP 5000     // 5000: adj duplicated pairs, ull[(s)*50+t] = (a,a)
#define OC    10000    // 5000: hA row-major -> hl row-major
#define OAGG  15000    // 5000: agg^T [d][s] -> later G row-major [s][d]
#define OSTAR 20000    // 100
#define OSKV  20100    // 100
#define OVV   20200    // 100
#define OGATE 20300    // 64
#define OMSK  20364    // 64
#define OALPH 20428    // 600
#define ONID  21028    // 600 (int)
#define OSNOD 21628    // 64 (int)
#define ODEN  21692    // 4
#define SMEM_FLOATS 21696
#define SMEM_BYTES  (SMEM_FLOATS * 4)

__global__ void __launch_bounds__(512, 2) k_main(
    const int*   __restrict__ inputs,
    const float* __restrict__ adjm,
    const int*   __restrict__ last_items,
    const int*   __restrict__ adj_items,
    const float* __restrict__ emb,
    const float* __restrict__ sp,
    const float* __restrict__ Wa,
    const float* __restrict__ Wq,
    const float* __restrict__ Wk,
    const float* __restrict__ Wg,
    const float* __restrict__ Wl,
    const int*   __restrict__ adj_all,
    const float* __restrict__ num_w,
    float* __restrict__ out)
{
    extern __shared__ float sm[];
    int tid = threadIdx.x;
    int bid = blockIdx.x;
    const float4* emb4 = (const float4*)emb;

    if (bid < BB) {
        // ============ combined star+global block, 2 concurrent halves ============
        int b = bid;
        float* A    = sm + OA;
        float* ADJP = sm + OADJP;
        float* C    = sm + OC;
        float* AGG  = sm + OAGG;   // later reused as G [s][d]
        float* star = sm + OSTAR;
        float* skv  = sm + OSKV;
        float* vv   = sm + OVV;
        float* gate = sm + OGATE;
        float* msk  = sm + OMSK;
        float* alph = sm + OALPH;
        int*   nid  = (int*)(sm + ONID);
        int*   snode= (int*)(sm + OSNOD);
        float* denp = sm + ODEN;

        if (tid < SS) {
            int nd = inputs[b * SS + tid];
            snode[tid] = nd;
            msk[tid] = (nd != 0) ? 1.f : 0.f;
        }
        __syncthreads();

        // ---- shared load phase (all 512 threads), vectorized gathers ----
        if (tid == 0) {
            float c = 0.f;
            #pragma unroll
            for (int s = 0; s < SS; s++) c += msk[s];
            denp[0] = fmaxf(c, 1.f);
        }
        // h gather: LDG.128, transpose-store into A[d][s]
        for (int i = tid; i < SS * 25; i += 512) {
            int s = i / 25, q = i - s * 25;
            float4 v = emb4[(ll)snode[s] * 25 + q];
            int d = 4 * q;
            A[(d + 0) * SS + s] = v.x;
            A[(d + 1) * SS + s] = v.y;
            A[(d + 2) * SS + s] = v.z;
            A[(d + 3) * SS + s] = v.w;
        }
        // adj duplicated pairs
        {
            const float* ab = adjm + (ll)b * SS * SS;
            float2* P = (float2*)ADJP;
            for (int i = tid; i < SS * SS; i += 512) {
                float a = ab[i];
                P[i] = make_float2(a, a);
            }
        }
        for (int i = tid; i < SS * NSN; i += 512) {
            int s = i / NSN, n = i - s * NSN;
            ll nd = snode[s];
            nid[i]  = adj_all[nd * NSN + n];
            alph[i] = num_w[nd * NSN + n];
        }
        __syncthreads();

        if (tid < 256) {
            // ======================= STAR half (barrier 1) =======================
            int st = tid;
            // P2: star = masked mean
            if (st < DD) {
                float s = 0.f;
                #pragma unroll 5
                for (int r = 0; r < SS; r++) s = fmaf(A[st * SS + r], msk[r], s);
                star[st] = s / denp[0];
            }
            barn(1);
            // P3: skv = star @ Wk
            if (st < DD) {
                float a0 = 0.f, a1 = 0.f, a2 = 0.f, a3 = 0.f;
                #pragma unroll 1
                for (int i = 0; i < DD; i += 4) {
                    a0 = fmaf(star[i],     Wk[i * DD + st],       a0);
                    a1 = fmaf(star[i + 1], Wk[(i + 1) * DD + st], a1);
                    a2 = fmaf(star[i + 2], Wk[(i + 2) * DD + st], a2);
                    a3 = fmaf(star[i + 3], Wk[(i + 3) * DD + st], a3);
                }
                skv[st] = (a0 + a1) + (a2 + a3);
            }
            barn(1);
            // P4: vv = Wq @ skv
            if (st < DD) {
                float a0 = 0.f, a1 = 0.f, a2 = 0.f, a3 = 0.f;
                const float* wr = Wq + st * DD;
                #pragma unroll 1
                for (int j = 0; j < DD; j += 4) {
                    a0 = fmaf(wr[j],     skv[j],     a0);
                    a1 = fmaf(wr[j + 1], skv[j + 1], a1);
                    a2 = fmaf(wr[j + 2], skv[j + 2], a2);
                    a3 = fmaf(wr[j + 3], skv[j + 3], a3);
                }
                vv[st] = (a0 + a1) + (a2 + a3);
            }
            barn(1);
            // P5: gate (st<50) + GEMM1 hA = h @ Wa (st<250) -> C
            if (st < SS) {
                float a = 0.f;
                #pragma unroll 4
                for (int d = 0; d < DD; d++) a = fmaf(A[d * SS + st], vv[d], a);
                gate[st] = 1.f / (1.f + expf(-a * SCALEF));
            }
            if (st < 250) {
                int c2 = st % 50, g = st / 50, r0 = g * 10;
                ull acc[5][2];
                #pragma unroll
                for (int rp = 0; rp < 5; rp++) { acc[rp][0] = 0ull; acc[rp][1] = 0ull; }
                const ull* Au = (const ull*)A;
                #pragma unroll 2
                for (int k = 0; k < DD; k++) {
                    float2 w = *(const float2*)&Wa[k * DD + 2 * c2];
                    ull wlo = pack2(w.x, w.x), whi = pack2(w.y, w.y);
                    const ull* xr = Au + k * (SS / 2) + g * 5;
                    #pragma unroll
                    for (int rp = 0; rp < 5; rp++) {
                        ull xp = xr[rp];
                        ffma2(acc[rp][0], xp, wlo);
                        ffma2(acc[rp][1], xp, whi);
                    }
                }
                #pragma unroll
                for (int rp = 0; rp < 5; rp++) {
                    float v0, v1, u0, u1;
                    unpack2(acc[rp][0], v0, v1);
                    unpack2(acc[rp][1], u0, u1);
                    int r = r0 + 2 * rp;
                    C[r * DD + 2 * c2]           = v0;
                    C[(r + 1) * DD + 2 * c2]     = v1;
                    C[r * DD + 2 * c2 + 1]       = u0;
                    C[(r + 1) * DD + 2 * c2 + 1] = u1;
                }
            }
            barn(1);
            // P6: hn = adj @ hA, hl = (1-g)*hn + g*star (ADJP pre-duplicated)
            float hlv[10][2];
            int dp = st % 50, sg = st / 50, s0r = sg * 10;
            if (st < 250) {
                ull hn[10];
                #pragma unroll
                for (int j = 0; j < 10; j++) hn[j] = 0ull;
                const ull* Cu = (const ull*)C;
                const ull* Pu = (const ull*)ADJP;
                #pragma unroll 2
                for (int t = 0; t < SS; t++) {
                    ull xp = Cu[t * (DD / 2) + dp];
                    const ull* pr = Pu + s0r * SS + t;
                    #pragma unroll
                    for (int j = 0; j < 10; j++)
                        ffma2(hn[j], xp, pr[j * SS]);
                }
                float st0 = star[2 * dp], st1 = star[2 * dp + 1];
                #pragma unroll
                for (int j = 0; j < 10; j++) {
                    float h0, h1;
                    unpack2(hn[j], h0, h1);
                    float gg = gate[s0r + j];
                    hlv[j][0] = (1.f - gg) * h0 + gg * st0;
                    hlv[j][1] = (1.f - gg) * h1 + gg * st1;
                }
            }
            barn(1);   // all reads of C done
            if (st < 250) {
                #pragma unroll
                for (int j = 0; j < 10; j++) {
                    C[(s0r + j) * DD + 2 * dp]     = hlv[j][0];
                    C[(s0r + j) * DD + 2 * dp + 1] = hlv[j][1];
                }
            }
        } else {
            // ====================== GLOBAL half (barrier 2) ======================
            int gt = tid - 256;
            // softmax over neighbor weights
            if (gt < SS) {
                float* ar = alph + gt * NSN;
                float m = ar[0];
                #pragma unroll
                for (int n = 1; n < NSN; n++) m = fmaxf(m, ar[n]);
                float e[NSN], ssum = 0.f;
                #pragma unroll
                for (int n = 0; n < NSN; n++) { e[n] = expf(ar[n] - m); ssum += e[n]; }
                float inv = 1.f / ssum;
                #pragma unroll
                for (int n = 0; n < NSN; n++) ar[n] = e[n] * inv;
            }
            barn(2);
            // agg gather: LDG.128 per neighbor row (12 per float4 of output)
            for (int i = gt; i < SS * 25; i += 256) {
                int s = i / 25, q = i - s * 25;
                const float* ar = alph + s * NSN;
                const int*   nr = nid + s * NSN;
                float ax = 0.f, ay = 0.f, az = 0.f, aw = 0.f;
                #pragma unroll
                for (int n = 0; n < NSN; n++) {
                    float4 e = emb4[(ll)nr[n] * 25 + q];
                    float al = ar[n];
                    ax = fmaf(al, e.x, ax);
                    ay = fmaf(al, e.y, ay);
                    az = fmaf(al, e.z, az);
                    aw = fmaf(al, e.w, aw);
                }
                int d = 4 * q;
                AGG[(d + 0) * SS + s] = ax;
                AGG[(d + 1) * SS + s] = ay;
                AGG[(d + 2) * SS + s] = az;
                AGG[(d + 3) * SS + s] = aw;
            }
            barn(2);
            // GEMM2: G = relu([h|agg] @ Wg), accumulate in regs
            ull acc[5][2];
            int c2 = gt % 50, g = gt / 50, r0 = g * 10;
            if (gt < 250) {
                #pragma unroll
                for (int rp = 0; rp < 5; rp++) { acc[rp][0] = 0ull; acc[rp][1] = 0ull; }
                const ull* Au = (const ull*)A;
                const ull* Bu = (const ull*)AGG;
                #pragma unroll 2
                for (int k = 0; k < DD; k++) {
                    float2 w = *(const float2*)&Wg[k * DD + 2 * c2];
                    ull wlo = pack2(w.x, w.x), whi = pack2(w.y, w.y);
                    const ull* xr = Au + k * (SS / 2) + g * 5;
                    #pragma unroll
                    for (int rp = 0; rp < 5; rp++) {
                        ull xp = xr[rp];
                        ffma2(acc[rp][0], xp, wlo);
                        ffma2(acc[rp][1], xp, whi);
                    }
                }
                #pragma unroll 2
                for (int k = 0; k < DD; k++) {
                    float2 w = *(const float2*)&Wg[(DD + k) * DD + 2 * c2];
                    ull wlo = pack2(w.x, w.x), whi = pack2(w.y, w.y);
                    const ull* xr = Bu + k * (SS / 2) + g * 5;
                    #pragma unroll
                    for (int rp = 0; rp < 5; rp++) {
                        ull xp = xr[rp];
                        ffma2(acc[rp][0], xp, wlo);
                        ffma2(acc[rp][1], xp, whi);
                    }
                }
            }
            barn(2);   // all AGG reads complete -> safe to overwrite with G
            if (gt < 250) {
                float* G = AGG;   // reuse
                #pragma unroll
                for (int rp = 0; rp < 5; rp++) {
                    float v0, v1, u0, u1;
                    unpack2(acc[rp][0], v0, v1);
                    unpack2(acc[rp][1], u0, u1);
                    int r = r0 + 2 * rp;
                    G[r * DD + 2 * c2]           = fmaxf(v0, 0.f);
                    G[(r + 1) * DD + 2 * c2]     = fmaxf(v1, 0.f);
                    G[r * DD + 2 * c2 + 1]       = fmaxf(u0, 0.f);
                    G[(r + 1) * DD + 2 * c2 + 1] = fmaxf(u1, 0.f);
                }
            }
        }
        __syncthreads();   // halves rendezvous: C = hl, AGG = G

        // ---- final combine: out = s0*l2n(hl) + s1*l2n(G) (all 16 warps) ----
        float* G = AGG;
        float s0 = sp[0], s1 = sp[1];
        int w = tid >> 5, lane = tid & 31;
        for (int r = w; r < SS; r += 16) {
            float ql = 0.f, qg = 0.f;
            for (int d = lane; d < DD; d += 32) {
                float x = C[r * DD + d]; ql = fmaf(x, x, ql);
                float y = G[r * DD + d]; qg = fmaf(y, y, qg);
            }
            #pragma unroll
            for (int o = 16; o > 0; o >>= 1) {
                ql += __shfl_xor_sync(0xffffffffu, ql, o);
                qg += __shfl_xor_sync(0xffffffffu, qg, o);
            }
            float il = s0 / fmaxf(sqrtf(ql), 1e-12f);
            float ig = s1 / fmaxf(sqrtf(qg), 1e-12f);
            ll base = ((ll)b * SS + r) * DD;
            for (int d = lane; d < DD; d += 32)
                out[base + d] = C[r * DD + d] * il + G[r * DD + d] * ig;
        }
    } else {
        // ========================== LAST family ==========================
        int b = bid - BB;
        float* ith = sm;            // 300
        float* ah  = sm + 300;      // 3600
        float* q   = sm + 3900;     // 300
        float* att = sm + 4200;     // 36
        float* out_last = out + (ll)BB * SS * DD;

        for (int i = tid; i < LASTN * 25; i += 512) {
            int l = i / 25, qq = i - l * 25;
            ((float4*)ith)[i] = emb4[(ll)last_items[b * LASTN + l] * 25 + qq];
        }
        for (int i = tid; i < LASTN * NADJN * 25; i += 512) {
            int n = i / 25, qq = i - n * 25;
            ((float4*)ah)[i] = emb4[(ll)adj_items[b * LASTN * NADJN + n] * 25 + qq];
        }
        __syncthreads();

        if (tid < DD) {
            #pragma unroll
            for (int l = 0; l < LASTN; l++) {
                float a = 0.f;
                #pragma unroll 4
                for (int k = 0; k < DD; k++)
                    a = fmaf(ith[l * DD + k], Wl[k * DD + tid], a);
                q[l * DD + tid] = a;
            }
        }
        __syncthreads();

        int w = tid >> 5, lane = tid & 31;
        for (int p = w; p < LASTN * NADJN; p += 16) {
            int l = p / NADJN;
            float s = 0.f;
            for (int d = lane; d < DD; d += 32)
                s = fmaf(q[l * DD + d], ah[p * DD + d], s);
            #pragma unroll
            for (int o = 16; o > 0; o >>= 1)
                s += __shfl_xor_sync(0xffffffffu, s, o);
            if (lane == 0) att[p] = s * SCALEF;
        }
        __syncthreads();

        if (tid < LASTN) {
            float* ar = att + tid * NADJN;
            float m = ar[0];
            #pragma unroll
            for (int n = 1; n < NADJN; n++) m = fmaxf(m, ar[n]);
            float e[NADJN], s = 0.f;
            #pragma unroll
            for (int n = 0; n < NADJN; n++) { e[n] = expf(ar[n] - m); s += e[n]; }
            float inv = 1.f / s;
            #pragma unroll
            for (int n = 0; n < NADJN; n++) ar[n] = e[n] * inv;
        }
        __syncthreads();

        if (tid < DD) {
            float acc = 0.f;
            #pragma unroll
            for (int l = 0; l < LASTN; l++) {
                float a = ith[l * DD + tid];
                #pragma unroll
                for (int n = 0; n < NADJN; n++)
                    a = fmaf(att[l * NADJN + n], ah[(l * NADJN + n) * DD + tid], a);
                acc += a;
            }
            out_last[(ll)b * DD + tid] = acc * (1.f / 3.f);
        }
    }
}

extern "C" void kernel_launch(void* const* d_in, const int* in_sizes, int n_in,
                              void* d_out, int out_size)
{
    const int*   inputs     = (const int*)d_in[0];
    const float* adjm       = (const float*)d_in[1];
    /* d_in[2] = item (unused by the reference) */
    const int*   last_items = (const int*)d_in[3];
    const int*   adj_items  = (const int*)d_in[4];
    const float* emb        = (const float*)d_in[5];
    const float* sp         = (const float*)d_in[6];
    const float* Wa         = (const float*)d_in[7];
    const float* Wq         = (const float*)d_in[8];
    const float* Wk         = (const float*)d_in[9];
    const float* Wg         = (const float*)d_in[10];
    const float* Wl         = (const float*)d_in[11];
    const int*   adj_all    = (const int*)d_in[12];
    const float* num_w      = (const float*)d_in[13];
    float* out = (float*)d_out;

    cudaFuncSetAttribute(k_main, cudaFuncAttributeMaxDynamicSharedMemorySize,
                         SMEM_BYTES);
    k_main<<<2 * BB, 512, SMEM_BYTES>>>(inputs, adjm, last_items, adj_items,
                                        emb, sp, Wa, Wq, Wk, Wg, Wl,
                                        adj_all, num_w, out);
}